// round 10
// baseline (speedup 1.0000x reference)
#include <cuda_runtime.h>

// Time-varying FIR via packed fma.rn.f32x2 (Blackwell FFMA2).
//   y[t] = sum_{k=0..49} x[t-k]*(bL[n][k] + w*(bR[n][k]-bL[n][k]))
//   n = t/80, w = (t%80)/80, x zero-padded left, right frame clamped.
// Two-accumulator split y = A0 + w*A1, outputs packed in pairs (R=10 -> 5 pairs).
// SINGLE shared x image: even-parity pairs come from aligned LDS.64; odd-parity
// pairs are synthesized with one register MOV from the same shift chain
// (wb_new = {u_tail_old.hi, u_tail_new.lo}), eliminating the second image.

#define BATCH     8
#define N_FRAMES  3000
#define FPERIOD   80
#define T_LEN     (N_FRAMES * FPERIOD)   // 240000
#define TAPS      50
#define ORD       49

#define FPB       20                     // frames per block (3000/20 = 150)
#define SPB       (FPB * FPERIOD)        // 1600
#define R         10                     // samples per thread (5 packed pairs)
#define TPF       (FPERIOD / R)          // 8 threads per frame
#define THREADS   (FPB * TPF)            // 160 = 5 warps

#define SX_LEN    1664                   // 52 pad + 1600 + spare (float4 staged)

typedef unsigned long long ull;

__device__ __forceinline__ ull fma2(ull a, ull b, ull c) {
    ull d;
    asm("fma.rn.f32x2 %0, %1, %2, %3;" : "=l"(d) : "l"(a), "l"(b), "l"(c));
    return d;
}
__device__ __forceinline__ ull pack2(float lo, float hi) {
    ull d;
    asm("mov.b64 %0, {%1, %2};" : "=l"(d) : "f"(lo), "f"(hi));
    return d;
}
// {hi word of a, lo word of b} -> one packed pair (x[q], x[q+1]) at odd q
__device__ __forceinline__ ull comb(ull a, ull b) {
    ull d;
    asm("{\n\t"
        ".reg .b32 al, ah, bl, bh;\n\t"
        "mov.b64 {al, ah}, %1;\n\t"
        "mov.b64 {bl, bh}, %2;\n\t"
        "mov.b64 %0, {ah, bl};\n\t"
        "}" : "=l"(d) : "l"(a), "l"(b));
    return d;
}
__device__ __forceinline__ ull lds64(const float* p) {
    return *(const ull*)p;               // 8B-aligned by construction
}

__global__ __launch_bounds__(THREADS, 6)
void azdf_kernel(const float* __restrict__ x,
                 const float* __restrict__ b,
                 float* __restrict__ y)
{
    __shared__ __align__(16) float  sxA[SX_LEN];       // sxA[i] = x[t0-52+i]
    __shared__ __align__(16) float4 sc4[FPB * TAPS];   // (c49,c49,d49,d49) per tap

    const int tid = threadIdx.x;
    const int bb  = blockIdx.y;
    const int f0  = blockIdx.x * FPB;
    const int t0  = f0 * FPERIOD;

    const float* xb  = x + (size_t)bb * T_LEN;
    const float* bbp = b + (size_t)bb * N_FRAMES * TAPS;

    // --- stage x image (float4 global loads, edge-guarded) ---
    for (int i4 = tid * 4; i4 < SX_LEN; i4 += THREADS * 4) {
        int g = t0 - 52 + i4;
        float4 v;
        if (g >= 0 && g + 3 < T_LEN) {
            v = *(const float4*)(xb + g);
        } else {
            v.x = (g + 0 >= 0 && g + 0 < T_LEN) ? xb[g + 0] : 0.0f;
            v.y = (g + 1 >= 0 && g + 1 < T_LEN) ? xb[g + 1] : 0.0f;
            v.z = (g + 2 >= 0 && g + 2 < T_LEN) ? xb[g + 2] : 0.0f;
            v.w = (g + 3 >= 0 && g + 3 < T_LEN) ? xb[g + 3] : 0.0f;
        }
        *(float4*)&sxA[i4] = v;
    }
    // --- stage reversed coeffs duplicated: sc4[f][j] = (bL,bL,d,d), j = 49-k ---
    for (int i = tid; i < FPB * TAPS; i += THREADS) {
        int f = i / TAPS;
        int j = i - f * TAPS;
        int k = ORD - j;
        float bl = bbp[(f0 + f) * TAPS + k];
        int f1 = f0 + f + 1;
        if (f1 > N_FRAMES - 1) f1 = N_FRAMES - 1;
        float br = bbp[f1 * TAPS + k];
        float4 q;
        q.x = bl; q.y = bl; q.z = br - bl; q.w = br - bl;
        sc4[f * TAPS + j] = q;
    }
    __syncthreads();

    const int fi  = tid / TPF;            // frame within block
    const int sub = tid - fi * TPF;       // thread within frame
    const int p0  = sub * R;              // phase of first sample (even)
    const int s   = fi * FPERIOD + p0;    // first sample offset in block (even)

    // Output pair m in {0..4} covers samples (s+2m, s+2m+1).
    // Tap j operand pair starts at sxA-index q = s + 2m + j + 3:
    //   j = 2a   (even) -> q odd  -> wb_m  = {U_{m+a}.hi, U_{m+a+1}.lo}
    //   j = 2a+1 (odd)  -> q even -> wa_m  = U_{m+a+1}
    // where U_i = (sxA[s+2+2i], sxA[s+3+2i]) as a 64-bit pair.
    ull A00=0, A01=0, A02=0, A03=0, A04=0;    // sum x*bL
    ull A10=0, A11=0, A12=0, A13=0, A14=0;    // sum x*diff

    // init chains at a=0: u1..u5 = U_1..U_5 ; b0..b4 = comb(U_m, U_{m+1})
    ull u0 = lds64(&sxA[s + 2]);
    ull u1 = lds64(&sxA[s + 4]);
    ull u2 = lds64(&sxA[s + 6]);
    ull u3 = lds64(&sxA[s + 8]);
    ull u4 = lds64(&sxA[s + 10]);
    ull u5 = lds64(&sxA[s + 12]);
    ull b0 = comb(u0, u1);
    ull b1 = comb(u1, u2);
    ull b2 = comb(u2, u3);
    ull b3 = comb(u3, u4);
    ull b4 = comb(u4, u5);

    const ulonglong2* cp = (const ulonglong2*)(sc4 + fi * TAPS);

    #pragma unroll
    for (int a = 0; a < TAPS / 2; a++) {          // taps j = 2a, 2a+1
        ulonglong2 ce = cp[2 * a];                // even tap: .x=(c,c) .y=(d,d)
        ulonglong2 co = cp[2 * a + 1];            // odd tap

        A00 = fma2(b0, ce.x, A00);  A10 = fma2(b0, ce.y, A10);
        A01 = fma2(b1, ce.x, A01);  A11 = fma2(b1, ce.y, A11);
        A02 = fma2(b2, ce.x, A02);  A12 = fma2(b2, ce.y, A12);
        A03 = fma2(b3, ce.x, A03);  A13 = fma2(b3, ce.y, A13);
        A04 = fma2(b4, ce.x, A04);  A14 = fma2(b4, ce.y, A14);

        A00 = fma2(u1, co.x, A00);  A10 = fma2(u1, co.y, A10);
        A01 = fma2(u2, co.x, A01);  A11 = fma2(u2, co.y, A11);
        A02 = fma2(u3, co.x, A02);  A12 = fma2(u3, co.y, A12);
        A03 = fma2(u4, co.x, A03);  A13 = fma2(u4, co.y, A13);
        A04 = fma2(u5, co.x, A04);  A14 = fma2(u5, co.y, A14);

        if (a < TAPS / 2 - 1) {
            ull nu = lds64(&sxA[s + 14 + 2 * a]); // U_{a+6}
            ull nb = comb(u5, nu);                // wb tail for next iter
            u1 = u2; u2 = u3; u3 = u4; u4 = u5; u5 = nu;
            b0 = b1; b1 = b2; b2 = b3; b3 = b4; b4 = nb;
        }
    }

    // epilogue: y = A0 + (phase/80)*A1 ; five 8B stores (s even -> aligned)
    const float inv = 1.0f / FPERIOD;
    ull* yo = (ull*)(y + (size_t)bb * T_LEN + t0 + s);
    yo[0] = fma2(pack2((float)(p0 + 0) * inv, (float)(p0 + 1) * inv), A10, A00);
    yo[1] = fma2(pack2((float)(p0 + 2) * inv, (float)(p0 + 3) * inv), A11, A01);
    yo[2] = fma2(pack2((float)(p0 + 4) * inv, (float)(p0 + 5) * inv), A12, A02);
    yo[3] = fma2(pack2((float)(p0 + 6) * inv, (float)(p0 + 7) * inv), A13, A03);
    yo[4] = fma2(pack2((float)(p0 + 8) * inv, (float)(p0 + 9) * inv), A14, A04);
}

extern "C" void kernel_launch(void* const* d_in, const int* in_sizes, int n_in,
                              void* d_out, int out_size)
{
    const float* x = (const float*)d_in[0];
    const float* b = (const float*)d_in[1];
    if (in_sizes[0] != BATCH * T_LEN) {   // defensive input-order check
        const float* t = x; x = b; b = t;
    }
    dim3 grid(N_FRAMES / FPB, BATCH);     // 150 x 8 = 1200 blocks
    azdf_kernel<<<grid, THREADS>>>(x, b, (float*)d_out);
}

// round 11
// speedup vs baseline: 1.1553x; 1.1553x over previous
#include <cuda_runtime.h>

// Time-varying FIR via packed fma.rn.f32x2, TAP-PAIR packing.
//   y[t] = sum_{k=0..49} x[t-k]*(bL[n][k] + w*(bR[n][k]-bL[n][k]))
//   n=t/80, w=(t%80)/80, left zero pad, right frame clamped.
// j-form: y[u] = sum_j sx[u+j]*c[j], c[j]=coef[49-j].  Packed over taps:
//   A[u] = sum_a (sx[u+2a],sx[u+2a+1]) .* (c[2a],c[2a+1]);  y = hadd(A0)+w*hadd(A1)
// Both FFMA2 operands are contiguous aligned pairs: coeff pairs load directly
// (no duplication), window pairs via LDS.64 (no packing/comb). Each thread does
// 5 outputs of one parity; diagonal pair-reuse gives a pure-rename shift chain.

#define BATCH     8
#define N_FRAMES  3000
#define FPERIOD   80
#define T_LEN     (N_FRAMES * FPERIOD)   // 240000
#define TAPS      50
#define ORD       49
#define NPAIR     (TAPS / 2)             // 25 tap-pairs

#define FPB       10                     // frames per block (3000/10 = 300)
#define SPB       (FPB * FPERIOD)        // 800
#define TPF       16                     // threads per frame: 8 even + 8 odd
#define THREADS   (FPB * TPF)            // 160 = 5 warps

#define SX_LEN    864                    // 52 left pad + 800 + spare, /4 exact

typedef unsigned long long ull;

__device__ __forceinline__ ull fma2(ull a, ull b, ull c) {
    ull d;
    asm("fma.rn.f32x2 %0, %1, %2, %3;" : "=l"(d) : "l"(a), "l"(b), "l"(c));
    return d;
}
__device__ __forceinline__ float hadd2(ull a) {
    float lo, hi;
    asm("mov.b64 {%0, %1}, %2;" : "=f"(lo), "=f"(hi) : "l"(a));
    return lo + hi;
}
__device__ __forceinline__ ull lds64(const float* p) {
    return *(const ull*)p;               // 8B-aligned by construction
}

__global__ __launch_bounds__(THREADS)
void azdf_kernel(const float* __restrict__ x,
                 const float* __restrict__ b,
                 float* __restrict__ y)
{
    __shared__ __align__(16) float  sxA[SX_LEN];     // sxA[i] = x[t0-52+i]
    __shared__ __align__(16) float  sxB[SX_LEN];     // sxB[i] = x[t0-51+i]
    __shared__ __align__(16) float4 sc4[FPB * NPAIR];// (cL[2a],cL[2a+1],d[2a],d[2a+1])

    const int tid = threadIdx.x;
    const int bb  = blockIdx.y;
    const int f0  = blockIdx.x * FPB;
    const int t0  = f0 * FPERIOD;

    const float* xb  = x + (size_t)bb * T_LEN;
    const float* bbp = b + (size_t)bb * N_FRAMES * TAPS;

    // --- stage both x images (float4 global loads, edge-guarded) ---
    for (int i4 = tid * 4; i4 < SX_LEN; i4 += THREADS * 4) {
        int g = t0 - 52 + i4;               // multiple of 4
        float4 v;
        if (g >= 0 && g + 3 < T_LEN) {
            v = *(const float4*)(xb + g);
        } else {
            v.x = (g + 0 >= 0 && g + 0 < T_LEN) ? xb[g + 0] : 0.0f;
            v.y = (g + 1 >= 0 && g + 1 < T_LEN) ? xb[g + 1] : 0.0f;
            v.z = (g + 2 >= 0 && g + 2 < T_LEN) ? xb[g + 2] : 0.0f;
            v.w = (g + 3 >= 0 && g + 3 < T_LEN) ? xb[g + 3] : 0.0f;
        }
        *(float4*)&sxA[i4] = v;
        if (i4 > 0) sxB[i4 - 1] = v.x;      // sxB[i] = sxA[i+1]
        sxB[i4]     = v.y;
        sxB[i4 + 1] = v.z;
        if (i4 + 2 < SX_LEN) sxB[i4 + 2] = v.w;
    }
    // --- stage reversed coeff PAIRS: sc4[f*25+a] = (cL[2a],cL[2a+1],d[2a],d[2a+1])
    //     with cL[j] = bL[f0+f][49-j], d[j] = bR-bL at tap 49-j ---
    for (int i = tid; i < FPB * NPAIR; i += THREADS) {
        int f = i / NPAIR;
        int a = i - f * NPAIR;
        int fg = f0 + f;
        int f1 = (fg + 1 < N_FRAMES) ? fg + 1 : N_FRAMES - 1;
        const float* bl = bbp + fg * TAPS;
        const float* br = bbp + f1 * TAPS;
        int k0 = ORD - 2 * a;               // tap for j=2a
        int k1 = k0 - 1;                    // tap for j=2a+1
        float4 q;
        q.x = bl[k0];
        q.y = bl[k1];
        q.z = br[k0] - bl[k0];
        q.w = br[k1] - bl[k1];
        sc4[i] = q;
    }
    __syncthreads();

    const int fi     = tid / TPF;           // frame within block
    const int r      = tid - fi * TPF;
    const int parity = r & 1;
    const int seg    = r >> 1;              // 0..7
    const int p0     = seg * 10 + parity;   // phase of first output in frame
    const int u0     = fi * FPERIOD + p0;   // first output offset in block

    // Operand pair for output u0+2m at tap-pair a lives at base[2*(m+a)]:
    //   even u0: base = &sxB[u0+2]  (u0+2 even -> aligned)
    //   odd  u0: base = &sxA[u0+3]  (u0+3 even -> aligned)
    const float* base = parity ? &sxA[u0 + 3] : &sxB[u0 + 2];

    ull A00=0, A01=0, A02=0, A03=0, A04=0;  // packed tap-sums vs bL
    ull A10=0, A11=0, A12=0, A13=0, A14=0;  // packed tap-sums vs diff

    ull w0 = lds64(base + 0);
    ull w1 = lds64(base + 2);
    ull w2 = lds64(base + 4);
    ull w3 = lds64(base + 6);
    ull w4 = lds64(base + 8);

    const ulonglong2* cp = (const ulonglong2*)(sc4 + fi * NPAIR);

    #pragma unroll
    for (int a = 0; a < NPAIR; a++) {
        ulonglong2 c = cp[a];               // .x = cL pair, .y = d pair

        A00 = fma2(w0, c.x, A00);  A10 = fma2(w0, c.y, A10);
        A01 = fma2(w1, c.x, A01);  A11 = fma2(w1, c.y, A11);
        A02 = fma2(w2, c.x, A02);  A12 = fma2(w2, c.y, A12);
        A03 = fma2(w3, c.x, A03);  A13 = fma2(w3, c.y, A13);
        A04 = fma2(w4, c.x, A04);  A14 = fma2(w4, c.y, A14);

        if (a < NPAIR - 1) {                // pure-copy shift: renamed by unroll
            w0 = w1; w1 = w2; w2 = w3; w3 = w4;
            w4 = lds64(base + 10 + 2 * a);
        }
    }

    // epilogue: y[u0+2m] = hadd(A0_m) + ((p0+2m)/80) * hadd(A1_m)
    const float inv = 1.0f / FPERIOD;
    float* yo = y + (size_t)bb * T_LEN + t0 + u0;
    yo[0] = fmaf((float)(p0 + 0) * inv, hadd2(A10), hadd2(A00));
    yo[2] = fmaf((float)(p0 + 2) * inv, hadd2(A11), hadd2(A01));
    yo[4] = fmaf((float)(p0 + 4) * inv, hadd2(A12), hadd2(A02));
    yo[6] = fmaf((float)(p0 + 6) * inv, hadd2(A13), hadd2(A03));
    yo[8] = fmaf((float)(p0 + 8) * inv, hadd2(A14), hadd2(A04));
}

extern "C" void kernel_launch(void* const* d_in, const int* in_sizes, int n_in,
                              void* d_out, int out_size)
{
    const float* x = (const float*)d_in[0];
    const float* b = (const float*)d_in[1];
    if (in_sizes[0] != BATCH * T_LEN) {   // defensive input-order check
        const float* t = x; x = b; b = t;
    }
    dim3 grid(N_FRAMES / FPB, BATCH);     // 300 x 8 = 2400 blocks
    azdf_kernel<<<grid, THREADS>>>(x, b, (float*)d_out);
}

// round 12
// speedup vs baseline: 1.1575x; 1.0019x over previous
#include <cuda_runtime.h>

// Time-varying FIR, scalar FFMA, two-accumulator split  y = A0 + w*A1.
//   y[t] = sum_{k=0..49} x[t-k]*(bL[n][k] + w*(bR[n][k]-bL[n][k]))
//   n=t/80, w=(t%80)/80, left zero pad, right frame clamped.
// R=8 samples/thread: each coefficient LDS.128 (2 taps of (c,d)) feeds 32 FFMA.
// 160 threads = 5 whole warps; launch_bounds(160,8) pins regs for 40 warps/SM.

#define BATCH     8
#define N_FRAMES  3000
#define FPERIOD   80
#define T_LEN     (N_FRAMES * FPERIOD)   // 240000
#define TAPS      50
#define ORD       49

#define FPB       16                     // frames per block (ragged last block)
#define SPB       (FPB * FPERIOD)        // 1280
#define R         8                      // samples per thread
#define TPF       (FPERIOD / R)          // 10 threads per frame
#define THREADS   (FPB * TPF)            // 160 = 5 warps
#define GRIDX     ((N_FRAMES + FPB - 1) / FPB)   // 188

#define SX_LEN    1344                   // 49 pad + 1280 + spare (mult of 4)

__global__ __launch_bounds__(THREADS, 8)
void azdf_kernel(const float* __restrict__ x,
                 const float* __restrict__ b,
                 float* __restrict__ y)
{
    __shared__ __align__(16) float sx[SX_LEN];          // sx[i] = x[t0-52+i]
    __shared__ __align__(16) float sc[FPB * TAPS * 2];  // (c49[j], d49[j]) pairs

    const int tid = threadIdx.x;
    const int bb  = blockIdx.y;
    const int f0  = blockIdx.x * FPB;
    const int t0  = f0 * FPERIOD;

    const float* xb  = x + (size_t)bb * T_LEN;
    const float* bbp = b + (size_t)bb * N_FRAMES * TAPS;

    // --- stage x window: sx[i] = x[t0-52+i] (52 keeps float4 alignment; we
    //     only ever read indices >= 3), edge-guarded float4 loads ---
    for (int i4 = tid * 4; i4 < SX_LEN; i4 += THREADS * 4) {
        int g = t0 - 52 + i4;
        float4 v;
        if (g >= 0 && g + 3 < T_LEN) {
            v = *(const float4*)(xb + g);
        } else {
            v.x = (g + 0 >= 0 && g + 0 < T_LEN) ? xb[g + 0] : 0.0f;
            v.y = (g + 1 >= 0 && g + 1 < T_LEN) ? xb[g + 1] : 0.0f;
            v.z = (g + 2 >= 0 && g + 2 < T_LEN) ? xb[g + 2] : 0.0f;
            v.w = (g + 3 >= 0 && g + 3 < T_LEN) ? xb[g + 3] : 0.0f;
        }
        *(float4*)&sx[i4] = v;
    }
    // --- stage reversed coeffs + diff: sc[f*100+2j] = bL[49-j], +1 = bR-bL ---
    for (int i = tid; i < FPB * TAPS; i += THREADS) {
        int f  = i / TAPS;
        int j  = i - f * TAPS;
        int fg = f0 + f;
        if (fg < N_FRAMES) {
            int k = ORD - j;
            float bl = bbp[fg * TAPS + k];
            int f1 = (fg + 1 < N_FRAMES) ? fg + 1 : N_FRAMES - 1;
            float br = bbp[f1 * TAPS + k];
            sc[f * (2 * TAPS) + 2 * j]     = bl;
            sc[f * (2 * TAPS) + 2 * j + 1] = br - bl;
        }
    }
    __syncthreads();

    const int fi  = tid / TPF;            // frame within block
    const int sub = tid - fi * TPF;       // thread within frame
    const int p0  = sub * R;              // phase of first sample in frame
    const int s   = fi * FPERIOD + p0;    // first sample offset (mult of 8)
    const bool active = (f0 + fi) < N_FRAMES;

    // j-form: y[s+m] = sum_j sx[3 + s + m + j] * c49[j]
    const int off = s + 3;                // sx index of x[t-49] for m=0, j=0

    float4 wa = *(const float4*)&sx[off + 1];   // off+1 .. off+4  (unaligned? off=s+3, s mult8 -> off+1 = s+4, aligned)
    // window w[m] holds sx[off + m + j] during tap j; init j=0:
    // need sx[off+0..off+7]; load via two float4 at off.. but off = s+3 not aligned.
    // Stage scalar loads for the 8-window init instead (one-time cost).
    float w0 = sx[off + 0], w1 = sx[off + 1], w2 = sx[off + 2], w3 = sx[off + 3];
    float w4 = sx[off + 4], w5 = sx[off + 5], w6 = sx[off + 6], w7 = sx[off + 7];
    (void)wa;

    float a00=0.f,a01=0.f,a02=0.f,a03=0.f,a04=0.f,a05=0.f,a06=0.f,a07=0.f;
    float a10=0.f,a11=0.f,a12=0.f,a13=0.f,a14=0.f,a15=0.f,a16=0.f,a17=0.f;

    const float4* cp = (const float4*)&sc[fi * (2 * TAPS)]; // 2 taps per vec4
    const float4* xq = (const float4*)&sx[s + 12];          // aligned prefetch:
    // sx[off + 8 + q] for q=0..  -> index s+11+q ; first aligned group at s+12
    float xlead = sx[s + 11];             // q=0 element (handled separately)

    float4 c, xp;
    #pragma unroll
    for (int j = 0; j < TAPS; j++) {
        if ((j & 1) == 0) c = cp[j >> 1];
        const float cb = (j & 1) ? c.z : c.x;
        const float cd = (j & 1) ? c.w : c.y;
        // prefetch group for incoming samples sx[s+12+4q]
        if ((j & 3) == 1) xp = xq[j >> 2];

        a00 = fmaf(w0, cb, a00);  a10 = fmaf(w0, cd, a10);
        a01 = fmaf(w1, cb, a01);  a11 = fmaf(w1, cd, a11);
        a02 = fmaf(w2, cb, a02);  a12 = fmaf(w2, cd, a12);
        a03 = fmaf(w3, cb, a03);  a13 = fmaf(w3, cd, a13);
        a04 = fmaf(w4, cb, a04);  a14 = fmaf(w4, cd, a14);
        a05 = fmaf(w5, cb, a05);  a15 = fmaf(w5, cd, a15);
        a06 = fmaf(w6, cb, a06);  a16 = fmaf(w6, cd, a16);
        a07 = fmaf(w7, cb, a07);  a17 = fmaf(w7, cd, a17);

        if (j < TAPS - 1) {
            // incoming sample for next tap: sx[off + 8 + j] = sx[s + 11 + j]
            float nx;
            if (j == 0) nx = xlead;
            else {
                const int ph = (j - 1) & 3;       // compile-time after unroll
                nx = (ph == 0) ? xp.x : (ph == 1) ? xp.y : (ph == 2) ? xp.z : xp.w;
            }
            w0 = w1; w1 = w2; w2 = w3; w3 = w4;
            w4 = w5; w5 = w6; w6 = w7; w7 = nx;
        }
    }

    if (active) {
        const float inv = 1.0f / FPERIOD;
        float* yo = y + (size_t)bb * T_LEN + t0 + s;
        float4 r0, r1;
        r0.x = fmaf((float)(p0 + 0) * inv, a10, a00);
        r0.y = fmaf((float)(p0 + 1) * inv, a11, a01);
        r0.z = fmaf((float)(p0 + 2) * inv, a12, a02);
        r0.w = fmaf((float)(p0 + 3) * inv, a13, a03);
        r1.x = fmaf((float)(p0 + 4) * inv, a14, a04);
        r1.y = fmaf((float)(p0 + 5) * inv, a15, a05);
        r1.z = fmaf((float)(p0 + 6) * inv, a16, a06);
        r1.w = fmaf((float)(p0 + 7) * inv, a17, a07);
        *(float4*)yo       = r0;
        *(float4*)(yo + 4) = r1;
    }
}

extern "C" void kernel_launch(void* const* d_in, const int* in_sizes, int n_in,
                              void* d_out, int out_size)
{
    const float* x = (const float*)d_in[0];
    const float* b = (const float*)d_in[1];
    if (in_sizes[0] != BATCH * T_LEN) {   // defensive input-order check
        const float* t = x; x = b; b = t;
    }
    dim3 grid(GRIDX, BATCH);              // 188 x 8
    azdf_kernel<<<grid, THREADS>>>(x, b, (float*)d_out);
}

// round 13
// speedup vs baseline: 1.3175x; 1.1382x over previous
#include <cuda_runtime.h>

// Time-varying FIR, scalar FFMA, two-accumulator split y = A0 + w*A1.
//   y[t] = sum_{k=0..49} x[t-k]*(bL[n][k] + w*(bR[n][k]-bL[n][k]))
//   n=t/80, w=(t%80)/80, left zero pad, right frame clamped.
// R4 winning geometry (FPB=8, R=4, 160 thr, grid 375x8) with software-pipelined
// shared loads: x-window groups and coefficient pairs are double-buffered so
// every LDS completes >=4 taps before first use (R4 exposed ~29cyc LDS latency
// every 4 taps by loading in the consuming tap). Staging is float4-vectorized.

#define BATCH     8
#define N_FRAMES  3000
#define FPERIOD   80
#define T_LEN     (N_FRAMES * FPERIOD)   // 240000
#define TAPS      50
#define ORD       49

#define FPB       8                      // frames per block (3000/8 = 375)
#define SPB       (FPB * FPERIOD)        // 640
#define R         4                      // samples per thread
#define TPF       (FPERIOD / R)          // 20 threads per frame
#define THREADS   (FPB * TPF)            // 160 = 5 warps

#define SX_LEN    704                    // 52 left pad + 640 + 12 spare (mult 4)

__global__ __launch_bounds__(THREADS, 8)
void azdf_kernel(const float* __restrict__ x,
                 const float* __restrict__ b,
                 float* __restrict__ y)
{
    __shared__ __align__(16) float sx[SX_LEN];          // sx[i] = x[t0-52+i]
    __shared__ __align__(16) float sc[FPB * TAPS * 2 + 4]; // (c49[j],d49[j]) pairs (+pad)

    const int tid = threadIdx.x;
    const int bb  = blockIdx.y;
    const int f0  = blockIdx.x * FPB;
    const int t0  = f0 * FPERIOD;

    const float* xb  = x + (size_t)bb * T_LEN;
    const float* bbp = b + (size_t)bb * N_FRAMES * TAPS;

    // --- stage x window, float4 global loads, edge-guarded ---
    for (int i4 = tid * 4; i4 < SX_LEN; i4 += THREADS * 4) {
        int g = t0 - 52 + i4;                 // multiple of 4 -> aligned
        float4 v;
        if (g >= 0 && g + 3 < T_LEN) {
            v = *(const float4*)(xb + g);
        } else {
            v.x = (g + 0 >= 0 && g + 0 < T_LEN) ? xb[g + 0] : 0.0f;
            v.y = (g + 1 >= 0 && g + 1 < T_LEN) ? xb[g + 1] : 0.0f;
            v.z = (g + 2 >= 0 && g + 2 < T_LEN) ? xb[g + 2] : 0.0f;
            v.w = (g + 3 >= 0 && g + 3 < T_LEN) ? xb[g + 3] : 0.0f;
        }
        *(float4*)&sx[i4] = v;
    }
    // --- stage reversed coeffs + diff: sc[f*100+2j] = bL[49-j], +1 = bR-bL ---
    for (int i = tid; i < FPB * TAPS; i += THREADS) {
        int f = i / TAPS;
        int j = i - f * TAPS;
        int k = ORD - j;
        float bl = bbp[(f0 + f) * TAPS + k];
        int f1 = f0 + f + 1;
        if (f1 > N_FRAMES - 1) f1 = N_FRAMES - 1;
        float br = bbp[f1 * TAPS + k];
        sc[f * (2 * TAPS) + 2 * j]     = bl;
        sc[f * (2 * TAPS) + 2 * j + 1] = br - bl;
    }
    __syncthreads();

    const int fi  = tid / TPF;            // frame within block
    const int sub = tid - fi * TPF;       // thread within frame
    const int p0  = sub * R;              // phase of first sample in frame
    const int s   = fi * FPERIOD + p0;    // first sample offset (mult of 4)

    // j-form: y[s+m] = sum_j sx[s+3+m+j] * c49[j]
    // window at tap j: w_m = sx[s+3+m+j]; shift-in element sx[s+7+j].
    float w0 = sx[s + 3], w1 = sx[s + 4], w2 = sx[s + 5], w3 = sx[s + 6];
    float xlead = sx[s + 7];              // shift-in for j=0

    float a00=0.f,a01=0.f,a02=0.f,a03=0.f;   // sum x*bL
    float a10=0.f,a11=0.f,a12=0.f,a13=0.f;   // sum x*diff

    const float4* cp = (const float4*)&sc[fi * (2 * TAPS)]; // 2 taps per vec4
    const float4* xq = (const float4*)&sx[s + 8];           // aligned groups:
    // group q covers shift-ins for taps j = 4q+1 .. 4q+4 (element (j-1)&3)

    // software pipeline: keep current + next buffers for both streams
    float4 c  = cp[0];
    float4 cn = cp[1];
    float4 xp = xq[0];
    float4 xpn = xq[1];

    #pragma unroll
    for (int j = 0; j < TAPS; j++) {
        if (j >= 2 && (j & 1) == 0) {
            c = cn;
            const int na = (j >> 1) + 1;          // next pair index
            cn = cp[(na < 25) ? na : 24];         // clamp (pad-safe)
        }
        const float cb = (j & 1) ? c.z : c.x;
        const float cd = (j & 1) ? c.w : c.y;

        if (j >= 5 && ((j - 1) & 3) == 0) {       // entering group q=(j-1)>>2
            xp = xpn;
            const int nq = ((j - 1) >> 2) + 1;
            xpn = xq[(nq < 13) ? nq : 12];        // clamp (stay in sx)
        }

        a00 = fmaf(w0, cb, a00);  a10 = fmaf(w0, cd, a10);
        a01 = fmaf(w1, cb, a01);  a11 = fmaf(w1, cd, a11);
        a02 = fmaf(w2, cb, a02);  a12 = fmaf(w2, cd, a12);
        a03 = fmaf(w3, cb, a03);  a13 = fmaf(w3, cd, a13);

        if (j < TAPS - 1) {
            float nx;
            if (j == 0) nx = xlead;
            else {
                const int ph = (j - 1) & 3;       // compile-time after unroll
                nx = (ph == 0) ? xp.x : (ph == 1) ? xp.y : (ph == 2) ? xp.z : xp.w;
            }
            w0 = w1; w1 = w2; w2 = w3; w3 = nx;
        }
    }

    // epilogue: y = A0 + (phase/80)*A1 ; one STG.128
    const float inv = 1.0f / FPERIOD;
    float4 r;
    r.x = fmaf((float)(p0 + 0) * inv, a10, a00);
    r.y = fmaf((float)(p0 + 1) * inv, a11, a01);
    r.z = fmaf((float)(p0 + 2) * inv, a12, a02);
    r.w = fmaf((float)(p0 + 3) * inv, a13, a03);
    *(float4*)(y + (size_t)bb * T_LEN + t0 + s) = r;
}

extern "C" void kernel_launch(void* const* d_in, const int* in_sizes, int n_in,
                              void* d_out, int out_size)
{
    const float* x = (const float*)d_in[0];
    const float* b = (const float*)d_in[1];
    if (in_sizes[0] != BATCH * T_LEN) {   // defensive input-order check
        const float* t = x; x = b; b = t;
    }
    dim3 grid(N_FRAMES / FPB, BATCH);     // 375 x 8 = 3000 blocks
    azdf_kernel<<<grid, THREADS>>>(x, b, (float*)d_out);
}